// round 11
// baseline (speedup 1.0000x reference)
#include <cuda_runtime.h>
#include <cuda_bf16.h>
#include <math.h>
#include <stdint.h>

#define NB     4096
#define NPER   2000
#define EPB    8                   // events (warps) per block
#define THREADS (EPB * 32)         // 256
#define NBLK   (NB / EPB)          // 512 blocks -> 3.46/SM, single wave at 4 blk/SM cap
#define CROWS  125                 // rows per event per chunk
#define CBYTES (CROWS * 16)        // 2000 B
#define STAGEB (EPB * CBYTES)      // 16000 B per stage
#define NCHUNK 16                  // 16 * 125 = 2000 rows
#define NSTAGE 3                   // 3 * 16000 = 48000 B static smem

// Scratch (no device allocation allowed anywhere).
__device__ double g_part[NBLK];
__device__ unsigned int g_cnt = 0;

#define ACCUM(v)                                   \
    do {                                           \
        acc[0] += (v).x; acc[1] += (v).y;          \
        acc[2] += (v).z; acc[3] += (v).w;          \
        acc[4]  = fmaf((v).x, (v).x, acc[4]);      \
        acc[5]  = fmaf((v).x, (v).y, acc[5]);      \
        acc[6]  = fmaf((v).x, (v).z, acc[6]);      \
        acc[7]  = fmaf((v).x, (v).w, acc[7]);      \
        acc[8]  = fmaf((v).y, (v).y, acc[8]);      \
        acc[9]  = fmaf((v).y, (v).z, acc[9]);      \
        acc[10] = fmaf((v).y, (v).w, acc[10]);     \
        acc[11] = fmaf((v).z, (v).z, acc[11]);     \
        acc[12] = fmaf((v).z, (v).w, acc[12]);     \
        acc[13] = fmaf((v).w, (v).w, acc[13]);     \
    } while (0)

__device__ __forceinline__ void mbar_init(uint32_t bar, uint32_t cnt) {
    asm volatile("mbarrier.init.shared.b64 [%0], %1;" :: "r"(bar), "r"(cnt) : "memory");
}
__device__ __forceinline__ void mbar_expect_tx(uint32_t bar, uint32_t bytes) {
    asm volatile("mbarrier.arrive.expect_tx.shared::cta.b64 _, [%0], %1;"
                 :: "r"(bar), "r"(bytes) : "memory");
}
__device__ __forceinline__ void bulk_ld(uint32_t dst_smem, const void* src_gmem,
                                        uint32_t bytes, uint32_t bar) {
    asm volatile(
        "cp.async.bulk.shared::cta.global.mbarrier::complete_tx::bytes "
        "[%0], [%1], %2, [%3];"
        :: "r"(dst_smem), "l"(src_gmem), "r"(bytes), "r"(bar) : "memory");
}
__device__ __forceinline__ void mbar_wait(uint32_t bar, uint32_t phase) {
    asm volatile(
        "{\n\t"
        ".reg .pred P;\n"
        "WAIT_%=:\n\t"
        "mbarrier.try_wait.parity.acquire.cta.shared::cta.b64 P, [%0], %1, 0x989680;\n\t"
        "@!P bra WAIT_%=;\n\t"
        "}"
        :: "r"(bar), "r"(phase) : "memory");
}

__global__ void __launch_bounds__(THREADS) llfill_fused_kernel(
        const float4* __restrict__ x, float* __restrict__ out) {
    __shared__ alignas(16) char sbuf[NSTAGE][STAGEB];   // 48000 B
    __shared__ alignas(8) uint64_t mbar[NSTAGE];
    __shared__ float spen[EPB];
    __shared__ double sred[EPB];
    __shared__ bool is_last;

    const int lane = threadIdx.x & 31;
    const int warp = threadIdx.x >> 5;                  // 0..7, one warp per event
    const char* gbase = (const char*)x + (size_t)blockIdx.x * EPB * NPER * 16;

    uint32_t bar_s[NSTAGE];
#pragma unroll
    for (int s = 0; s < NSTAGE; s++)
        bar_s[s] = (uint32_t)__cvta_generic_to_shared(&mbar[s]);
    const uint32_t sbuf0 = (uint32_t)__cvta_generic_to_shared(&sbuf[0][0]);

    if (threadIdx.x == 0) {
#pragma unroll
        for (int s = 0; s < NSTAGE; s++) mbar_init(bar_s[s], 1);
        asm volatile("fence.proxy.async.shared::cta;" ::: "memory");
    }
    __syncthreads();

    // Prime: chunks 0 and 1 into stages 0 and 1 (8 events x 2000 B each).
    if (threadIdx.x == 0) {
#pragma unroll
        for (int c = 0; c < 2; c++) {
            mbar_expect_tx(bar_s[c], STAGEB);
#pragma unroll
            for (int e = 0; e < EPB; e++)
                bulk_ld(sbuf0 + c * STAGEB + e * CBYTES,
                        gbase + ((size_t)e * NPER + (size_t)c * CROWS) * 16,
                        CBYTES, bar_s[c]);
        }
    }

    float acc[14];
#pragma unroll
    for (int j = 0; j < 14; j++) acc[j] = 0.0f;

    int stage = 0, kpar = 0;
#pragma unroll 1
    for (int c = 0; c < NCHUNK; c++) {
        // Producer: issue chunk c+2 into stage (c+2)%3. Safe: the __syncthreads
        // ending iter c-1 guarantees chunk c-1 (same stage) is fully consumed.
        if (threadIdx.x == 0 && c < NCHUNK - 2) {
            const int cn = c + 2;
            const int sn = (stage + 2 >= NSTAGE) ? stage - 1 : stage + 2;
            mbar_expect_tx(bar_s[sn], STAGEB);
#pragma unroll
            for (int e = 0; e < EPB; e++)
                bulk_ld(sbuf0 + sn * STAGEB + e * CBYTES,
                        gbase + ((size_t)e * NPER + (size_t)cn * CROWS) * 16,
                        CBYTES, bar_s[sn]);
        }

        // Consume chunk c (125 rows per event): wait TMA completion, then LDS.
        mbar_wait(bar_s[stage], kpar);
        const float4* sp = (const float4*)(sbuf[stage] + warp * CBYTES);
#pragma unroll
        for (int i = 0; i < 3; i++) {
            float4 vv = sp[lane + 32 * i];
            ACCUM(vv);
        }
        if (lane < 29) {
            float4 vv = sp[96 + lane];
            ACCUM(vv);
        }
        __syncthreads();

        if (++stage == NSTAGE) { stage = 0; kpar ^= 1; }
    }

    // Warp shuffle reduce of the 14 moments.
#pragma unroll
    for (int j = 0; j < 14; j++) {
        float s = acc[j];
#pragma unroll
        for (int off = 16; off; off >>= 1) s += __shfl_down_sync(0xffffffffu, s, off);
        acc[j] = s;
    }

    if (lane == 0) {
        const float invN = 1.0f / (float)NPER;
        const float m0 = acc[0] * invN, m1 = acc[1] * invN;
        const float m2 = acc[2] * invN, m3 = acc[3] * invN;

        // Covariance (symmetric), shifted by mu = trace/4 so tr(A)=0.
        float a00 = acc[4]  * invN - m0 * m0;
        float a01 = acc[5]  * invN - m0 * m1;
        float a02 = acc[6]  * invN - m0 * m2;
        float a03 = acc[7]  * invN - m0 * m3;
        float a11 = acc[8]  * invN - m1 * m1;
        float a12 = acc[9]  * invN - m1 * m2;
        float a13 = acc[10] * invN - m1 * m3;
        float a22 = acc[11] * invN - m2 * m2;
        float a23 = acc[12] * invN - m2 * m3;
        float a33 = acc[13] * invN - m3 * m3;

        const float mu = 0.25f * (a00 + a11 + a22 + a33);
        a00 -= mu; a11 -= mu; a22 -= mu; a33 -= mu;

        // p2 = tr(A^2).
        float offsq = a01*a01 + a02*a02 + a03*a03 + a12*a12 + a13*a13 + a23*a23;
        float p2 = a00*a00 + a11*a11 + a22*a22 + a33*a33 + 2.0f * offsq;

        // B = A^2 (symmetric).
        float b00 = a00*a00 + a01*a01 + a02*a02 + a03*a03;
        float b11 = a01*a01 + a11*a11 + a12*a12 + a13*a13;
        float b22 = a02*a02 + a12*a12 + a22*a22 + a23*a23;
        float b33 = a03*a03 + a13*a13 + a23*a23 + a33*a33;
        float b01 = a00*a01 + a01*a11 + a02*a12 + a03*a13;
        float b02 = a00*a02 + a01*a12 + a02*a22 + a03*a23;
        float b03 = a00*a03 + a01*a13 + a02*a23 + a03*a33;
        float b12 = a01*a02 + a11*a12 + a12*a22 + a13*a23;
        float b13 = a01*a03 + a11*a13 + a12*a23 + a13*a33;
        float b23 = a02*a03 + a12*a13 + a22*a23 + a23*a33;

        // p3 = tr(A^3); p4 = tr(A^4).
        float p3 = b00*a00 + b11*a11 + b22*a22 + b33*a33
                 + 2.0f * (b01*a01 + b02*a02 + b03*a03 + b12*a12 + b13*a13 + b23*a23);
        float p4 = b00*b00 + b11*b11 + b22*b22 + b33*b33
                 + 2.0f * (b01*b01 + b02*b02 + b03*b03 + b12*b12 + b13*b13 + b23*b23);

        // Char poly of trace-free A: l^4 + e2 l^2 - e3 l + e4 (Newton identities, e1=0).
        float e2 = -0.5f * p2;
        float e3 = p3 * (1.0f / 3.0f);
        float e4 = 0.25f * fmaf(0.5f * p2, p2, -p4);

        // Newton from below the smallest root (all roots real; tr=0 => lmin <= 0).
        float l = -sqrtf(p2) * 1.000001f - 1e-12f;
#pragma unroll
        for (int it = 0; it < 16; it++) {
            float t  = l * l;
            float pv = fmaf(t + e2, t, fmaf(-e3, l, e4));
            float dv = fmaf(fmaf(4.0f, t, 2.0f * e2), l, -e3);
            l -= __fdividef(pv, dv);
        }

        float eigmin = mu + l;                          // min eigenvalue of cov
        float r = mu / (eigmin + 1e-6f) - 1.0f;         // mean(eig) == trace/4 == mu
        spen[warp] = logf(fmaf(r, r, 1.0f));
    }
    __syncthreads();

    // Per-block partial (fixed order -> deterministic), last-block final reduce.
    if (threadIdx.x == 0) {
        double s = 0.0;
#pragma unroll
        for (int e = 0; e < EPB; e++) s += (double)spen[e];
        g_part[blockIdx.x] = s;
        __threadfence();
        unsigned int t = atomicInc(&g_cnt, NBLK - 1);   // wraps to 0 each launch
        is_last = (t == NBLK - 1);
    }
    __syncthreads();

    if (is_last) {
        // 256 threads reduce 512 doubles with a fixed tree (deterministic).
        volatile double* vp = g_part;
        const int tid = threadIdx.x;
        double v0 = vp[tid] + vp[tid + THREADS];
#pragma unroll
        for (int off = 16; off; off >>= 1) v0 += __shfl_down_sync(0xffffffffu, v0, off);
        if ((tid & 31) == 0) sred[tid >> 5] = v0;
        __syncthreads();
        if (tid == 0) {
            double tot = 0.0;
#pragma unroll
            for (int w = 0; w < EPB; w++) tot += sred[w];
            out[0] = (float)tot;
        }
    }
}

extern "C" void kernel_launch(void* const* d_in, const int* in_sizes, int n_in,
                              void* d_out, int out_size) {
    const float4* x = (const float4*)d_in[0];   // clust_space [B*NPER, 4], 16B rows
    // d_in[1] (batch_idx) is sorted with equal group sizes -> pure reshape, unused.
    llfill_fused_kernel<<<NBLK, THREADS>>>(x, (float*)d_out);
}

// round 12
// speedup vs baseline: 1.0790x; 1.0790x over previous
#include <cuda_runtime.h>
#include <cuda_bf16.h>
#include <math.h>
#include <stdint.h>

#define NB   4096
#define NPER 2000
#define WPB  4                    // warps (events) per block
#define THREADS (WPB * 32)        // 128
#define NBLK (NB / WPB)           // 1024 blocks: near-perfect wave balance
#define BATCH 6                   // front-batched LDG.128 per iteration
#define PEN_SCALE 35184372088832.0   // 2^45 fixed-point scale for penalties

// Scratch (no device allocation allowed anywhere).
__device__ unsigned long long g_sum = 0ull;   // fixed-point penalty sum
__device__ unsigned int g_cnt = 0;

#define ACCUM(v)                                   \
    do {                                           \
        acc[0] += (v).x; acc[1] += (v).y;          \
        acc[2] += (v).z; acc[3] += (v).w;          \
        acc[4]  = fmaf((v).x, (v).x, acc[4]);      \
        acc[5]  = fmaf((v).x, (v).y, acc[5]);      \
        acc[6]  = fmaf((v).x, (v).z, acc[6]);      \
        acc[7]  = fmaf((v).x, (v).w, acc[7]);      \
        acc[8]  = fmaf((v).y, (v).y, acc[8]);      \
        acc[9]  = fmaf((v).y, (v).z, acc[9]);      \
        acc[10] = fmaf((v).y, (v).w, acc[10]);     \
        acc[11] = fmaf((v).z, (v).z, acc[11]);     \
        acc[12] = fmaf((v).z, (v).w, acc[12]);     \
        acc[13] = fmaf((v).w, (v).w, acc[13]);     \
    } while (0)

__global__ void __launch_bounds__(THREADS, 7) llfill_fused_kernel(
        const float4* __restrict__ x, float* __restrict__ out) {
    const int lane = threadIdx.x & 31;
    const int warp = threadIdx.x >> 5;
    const int b = blockIdx.x * WPB + warp;          // one warp per event
    const float4* base = x + (size_t)b * NPER + lane;
    const char* evb = (const char*)(x + (size_t)b * NPER);

    // 14 accumulators: sums x,y,z,w; moments xx,xy,xz,xw,yy,yz,yw,zz,zw,ww
    float acc[14];
#pragma unroll
    for (int j = 0; j < 14; j++) acc[j] = 0.0f;

    // 2000 = 62*32 + 16.  62 = 10*BATCH + 2. Batch kk covers rows
    // [192*kk, 192*kk+192) = 3072 B = 24 x 128 B lines.
    float4 v[BATCH];
    for (int kk = 0; kk < 10; kk++) {
        // L2 prefetch for batch kk+2: issues DRAM requests one full round
        // ahead of consumption (L2 = staging buffer), decoupling DRAM demand
        // from warp wake-up phases. One predicated inst, 24 lines.
        if (kk < 8 && lane < 24) {
            const char* pf = evb + 3072 * (kk + 2) + lane * 128;
            asm volatile("prefetch.global.L2 [%0];" :: "l"(pf));
        }
        if (kk == 7 && lane < 10) {     // tail region rows 1920..1999 (1280 B)
            const char* pf = evb + 30720 + lane * 128;
            asm volatile("prefetch.global.L2 [%0];" :: "l"(pf));
        }
        const float4* p = base + (size_t)(32 * BATCH) * kk;
#pragma unroll
        for (int u = 0; u < BATCH; u++) v[u] = __ldg(p + 32 * u);
#pragma unroll
        for (int u = 0; u < BATCH; u++) ACCUM(v[u]);
    }
    {   // iterations 60, 61
        float4 a0 = __ldg(base + 32 * 60);
        float4 a1 = __ldg(base + 32 * 61);
        ACCUM(a0); ACCUM(a1);
    }
    if (lane < 16) {                                // 16-row tail
        float4 a = __ldg(x + (size_t)b * NPER + 1984 + lane);
        ACCUM(a);
    }

    // Warp shuffle reduce of the 14 moments.
#pragma unroll
    for (int j = 0; j < 14; j++) {
        float s = acc[j];
#pragma unroll
        for (int off = 16; off; off >>= 1) s += __shfl_down_sync(0xffffffffu, s, off);
        acc[j] = s;
    }

    __shared__ bool is_last;
    if (threadIdx.x == 0) is_last = false;

    if (lane == 0) {
        const float invN = 1.0f / (float)NPER;
        const float m0 = acc[0] * invN, m1 = acc[1] * invN;
        const float m2 = acc[2] * invN, m3 = acc[3] * invN;

        // Covariance (symmetric), shifted by mu = trace/4 so tr(A)=0.
        float a00 = acc[4]  * invN - m0 * m0;
        float a01 = acc[5]  * invN - m0 * m1;
        float a02 = acc[6]  * invN - m0 * m2;
        float a03 = acc[7]  * invN - m0 * m3;
        float a11 = acc[8]  * invN - m1 * m1;
        float a12 = acc[9]  * invN - m1 * m2;
        float a13 = acc[10] * invN - m1 * m3;
        float a22 = acc[11] * invN - m2 * m2;
        float a23 = acc[12] * invN - m2 * m3;
        float a33 = acc[13] * invN - m3 * m3;

        const float mu = 0.25f * (a00 + a11 + a22 + a33);
        a00 -= mu; a11 -= mu; a22 -= mu; a33 -= mu;

        // p2 = tr(A^2).
        float offsq = a01*a01 + a02*a02 + a03*a03 + a12*a12 + a13*a13 + a23*a23;
        float p2 = a00*a00 + a11*a11 + a22*a22 + a33*a33 + 2.0f * offsq;

        // B = A^2 (symmetric, 10 entries).
        float b00 = a00*a00 + a01*a01 + a02*a02 + a03*a03;
        float b11 = a01*a01 + a11*a11 + a12*a12 + a13*a13;
        float b22 = a02*a02 + a12*a12 + a22*a22 + a23*a23;
        float b33 = a03*a03 + a13*a13 + a23*a23 + a33*a33;
        float b01 = a00*a01 + a01*a11 + a02*a12 + a03*a13;
        float b02 = a00*a02 + a01*a12 + a02*a22 + a03*a23;
        float b03 = a00*a03 + a01*a13 + a02*a23 + a03*a33;
        float b12 = a01*a02 + a11*a12 + a12*a22 + a13*a23;
        float b13 = a01*a03 + a11*a13 + a12*a23 + a13*a33;
        float b23 = a02*a03 + a12*a13 + a22*a23 + a23*a33;

        // p3 = tr(A^3); p4 = tr(A^4).
        float p3 = b00*a00 + b11*a11 + b22*a22 + b33*a33
                 + 2.0f * (b01*a01 + b02*a02 + b03*a03 + b12*a12 + b13*a13 + b23*a23);
        float p4 = b00*b00 + b11*b11 + b22*b22 + b33*b33
                 + 2.0f * (b01*b01 + b02*b02 + b03*b03 + b12*b12 + b13*b13 + b23*b23);

        // Char poly of trace-free A: l^4 + e2 l^2 - e3 l + e4 (Newton identities, e1=0).
        float e2 = -0.5f * p2;
        float e3 = p3 * (1.0f / 3.0f);
        float e4 = 0.25f * fmaf(0.5f * p2, p2, -p4);

        // Newton from below the smallest root (all roots real; tr=0 => lmin <= 0).
        float l = -sqrtf(p2) * 1.000001f - 1e-12f;
#pragma unroll
        for (int it = 0; it < 16; it++) {
            float t  = l * l;
            float pv = fmaf(t + e2, t, fmaf(-e3, l, e4));
            float dv = fmaf(fmaf(4.0f, t, 2.0f * e2), l, -e3);
            l -= __fdividef(pv, dv);
        }

        float eigmin = mu + l;                          // min eigenvalue of cov
        float r = mu / (eigmin + 1e-6f) - 1.0f;         // mean(eig) == trace/4 == mu
        float pen = logf(fmaf(r, r, 1.0f));             // >= 0 always

        // Deterministic accumulation: fixed-point integer atomic — integer
        // addition is exactly order-independent, so the result is bit-stable
        // regardless of arrival order. pen <= ~1e-1, sum*2^45 << 2^63.
        unsigned long long q =
            (unsigned long long)__double2ll_rn((double)pen * PEN_SCALE);
        atomicAdd(&g_sum, q);
    }
    __syncthreads();   // all 4 warps' atomics issued before ticket

    if (threadIdx.x == 0) {
        __threadfence();
        unsigned int t = atomicInc(&g_cnt, NBLK - 1);   // wraps to 0 each launch
        is_last = (t == NBLK - 1);
    }
    __syncthreads();

    if (is_last && threadIdx.x == 0) {
        unsigned long long s =
            atomicAdd(&g_sum, 0ull);                    // read with atomic (coherent)
        out[0] = (float)((double)s / PEN_SCALE);
        g_sum = 0ull;                                   // restore invariant for replay
        __threadfence();
    }
}

extern "C" void kernel_launch(void* const* d_in, const int* in_sizes, int n_in,
                              void* d_out, int out_size) {
    const float4* x = (const float4*)d_in[0];   // clust_space [B*NPER, 4], 16B rows
    // d_in[1] (batch_idx) is sorted with equal group sizes -> pure reshape, unused.
    llfill_fused_kernel<<<NBLK, THREADS>>>(x, (float*)d_out);
}

// round 13
// speedup vs baseline: 1.0947x; 1.0145x over previous
#include <cuda_runtime.h>
#include <cuda_bf16.h>
#include <math.h>
#include <stdint.h>

#define NB   4096
#define NPER 2000
#define WPB  4                    // warps (events) per block
#define THREADS (WPB * 32)        // 128
#define NBLK (NB / WPB)           // 1024 blocks: near-perfect wave balance
#define BATCH 6                   // front-batched LDG.128 per iteration

// Scratch (no device allocation allowed anywhere).
__device__ double g_part[NBLK];
__device__ unsigned int g_cnt = 0;

#define ACCUM(v)                                   \
    do {                                           \
        acc[0] += (v).x; acc[1] += (v).y;          \
        acc[2] += (v).z; acc[3] += (v).w;          \
        acc[4]  = fmaf((v).x, (v).x, acc[4]);      \
        acc[5]  = fmaf((v).x, (v).y, acc[5]);      \
        acc[6]  = fmaf((v).x, (v).z, acc[6]);      \
        acc[7]  = fmaf((v).x, (v).w, acc[7]);      \
        acc[8]  = fmaf((v).y, (v).y, acc[8]);      \
        acc[9]  = fmaf((v).y, (v).z, acc[9]);      \
        acc[10] = fmaf((v).y, (v).w, acc[10]);     \
        acc[11] = fmaf((v).z, (v).z, acc[11]);     \
        acc[12] = fmaf((v).z, (v).w, acc[12]);     \
        acc[13] = fmaf((v).w, (v).w, acc[13]);     \
    } while (0)

__global__ void __launch_bounds__(THREADS, 7) llfill_fused_kernel(
        const float4* __restrict__ x, float* __restrict__ out) {
    const int lane = threadIdx.x & 31;
    const int warp = threadIdx.x >> 5;
    const int b = blockIdx.x * WPB + warp;          // one warp per event
    const float4* base = x + (size_t)b * NPER + lane;
    const char* evb = (const char*)(x + (size_t)b * NPER);

    // 14 accumulators: sums x,y,z,w; moments xx,xy,xz,xw,yy,yz,yw,zz,zw,ww
    float acc[14];
#pragma unroll
    for (int j = 0; j < 14; j++) acc[j] = 0.0f;

    // 2000 = 62*32 + 16.  62 = 10*BATCH + 2. Batch kk covers rows
    // [192*kk, 192*kk+192) = 3072 B = 24 x 128 B lines.
    float4 v[BATCH];
    for (int kk = 0; kk < 10; kk++) {
        // L2 prefetch for batch kk+2: DRAM requests issued one round ahead of
        // consumption (L2 = staging buffer); consuming LDGs then hit L2.
        if (kk < 8 && lane < 24) {
            const char* pf = evb + 3072 * (kk + 2) + lane * 128;
            asm volatile("prefetch.global.L2 [%0];" :: "l"(pf));
        }
        if (kk == 7 && lane < 10) {     // tail region rows 1920..1999 (1280 B)
            const char* pf = evb + 30720 + lane * 128;
            asm volatile("prefetch.global.L2 [%0];" :: "l"(pf));
        }
        const float4* p = base + (size_t)(32 * BATCH) * kk;
#pragma unroll
        for (int u = 0; u < BATCH; u++) v[u] = __ldg(p + 32 * u);
#pragma unroll
        for (int u = 0; u < BATCH; u++) ACCUM(v[u]);
    }
    {   // iterations 60, 61
        float4 a0 = __ldg(base + 32 * 60);
        float4 a1 = __ldg(base + 32 * 61);
        ACCUM(a0); ACCUM(a1);
    }
    if (lane < 16) {                                // 16-row tail
        float4 a = __ldg(x + (size_t)b * NPER + 1984 + lane);
        ACCUM(a);
    }

    // Warp shuffle reduce of the 14 moments.
#pragma unroll
    for (int j = 0; j < 14; j++) {
        float s = acc[j];
#pragma unroll
        for (int off = 16; off; off >>= 1) s += __shfl_down_sync(0xffffffffu, s, off);
        acc[j] = s;
    }

    __shared__ float spen[WPB];

    if (lane == 0) {
        const float invN = 1.0f / (float)NPER;
        const float m0 = acc[0] * invN, m1 = acc[1] * invN;
        const float m2 = acc[2] * invN, m3 = acc[3] * invN;

        // Covariance (symmetric), shifted by mu = trace/4 so tr(A)=0.
        float a00 = acc[4]  * invN - m0 * m0;
        float a01 = acc[5]  * invN - m0 * m1;
        float a02 = acc[6]  * invN - m0 * m2;
        float a03 = acc[7]  * invN - m0 * m3;
        float a11 = acc[8]  * invN - m1 * m1;
        float a12 = acc[9]  * invN - m1 * m2;
        float a13 = acc[10] * invN - m1 * m3;
        float a22 = acc[11] * invN - m2 * m2;
        float a23 = acc[12] * invN - m2 * m3;
        float a33 = acc[13] * invN - m3 * m3;

        const float mu = 0.25f * (a00 + a11 + a22 + a33);
        a00 -= mu; a11 -= mu; a22 -= mu; a33 -= mu;

        // p2 = tr(A^2).
        float offsq = a01*a01 + a02*a02 + a03*a03 + a12*a12 + a13*a13 + a23*a23;
        float p2 = a00*a00 + a11*a11 + a22*a22 + a33*a33 + 2.0f * offsq;

        // B = A^2 (symmetric, 10 entries).
        float b00 = a00*a00 + a01*a01 + a02*a02 + a03*a03;
        float b11 = a01*a01 + a11*a11 + a12*a12 + a13*a13;
        float b22 = a02*a02 + a12*a12 + a22*a22 + a23*a23;
        float b33 = a03*a03 + a13*a13 + a23*a23 + a33*a33;
        float b01 = a00*a01 + a01*a11 + a02*a12 + a03*a13;
        float b02 = a00*a02 + a01*a12 + a02*a22 + a03*a23;
        float b03 = a00*a03 + a01*a13 + a02*a23 + a03*a33;
        float b12 = a01*a02 + a11*a12 + a12*a22 + a13*a23;
        float b13 = a01*a03 + a11*a13 + a12*a23 + a13*a33;
        float b23 = a02*a03 + a12*a13 + a22*a23 + a23*a33;

        // p3 = tr(A^3); p4 = tr(A^4).
        float p3 = b00*a00 + b11*a11 + b22*a22 + b33*a33
                 + 2.0f * (b01*a01 + b02*a02 + b03*a03 + b12*a12 + b13*a13 + b23*a23);
        float p4 = b00*b00 + b11*b11 + b22*b22 + b33*b33
                 + 2.0f * (b01*b01 + b02*b02 + b03*b03 + b12*b12 + b13*b13 + b23*b23);

        // Char poly of trace-free A: l^4 + e2 l^2 - e3 l + e4 (Newton identities, e1=0).
        float e2 = -0.5f * p2;
        float e3 = p3 * (1.0f / 3.0f);
        float e4 = 0.25f * fmaf(0.5f * p2, p2, -p4);

        // Newton from below the smallest root (all roots real; tr=0 => lmin <= 0).
        float l = -sqrtf(p2) * 1.000001f - 1e-12f;
#pragma unroll
        for (int it = 0; it < 16; it++) {
            float t  = l * l;
            float pv = fmaf(t + e2, t, fmaf(-e3, l, e4));
            float dv = fmaf(fmaf(4.0f, t, 2.0f * e2), l, -e3);
            l -= __fdividef(pv, dv);
        }

        float eigmin = mu + l;                          // min eigenvalue of cov
        float r = mu / (eigmin + 1e-6f) - 1.0f;         // mean(eig) == trace/4 == mu
        spen[warp] = logf(fmaf(r, r, 1.0f));
    }
    __syncthreads();

    // Per-block partial (fixed order -> deterministic), last-block final reduce.
    __shared__ bool is_last;
    if (threadIdx.x == 0) {
        double s = 0.0;
#pragma unroll
        for (int w = 0; w < WPB; w++) s += (double)spen[w];
        g_part[blockIdx.x] = s;
        __threadfence();
        unsigned int t = atomicInc(&g_cnt, NBLK - 1);   // wraps to 0 each launch
        is_last = (t == NBLK - 1);
    }
    __syncthreads();

    if (is_last) {
        // 128 threads reduce 1024 doubles with a fixed tree (deterministic).
        volatile double* vp = g_part;
        const int tid = threadIdx.x;
        double v0 = 0.0;
#pragma unroll
        for (int i = 0; i < NBLK / THREADS; i++) v0 += vp[tid + i * THREADS];
#pragma unroll
        for (int off = 16; off; off >>= 1) v0 += __shfl_down_sync(0xffffffffu, v0, off);
        __shared__ double sred[WPB];
        if ((tid & 31) == 0) sred[tid >> 5] = v0;
        __syncthreads();
        if (tid == 0) {
            double tot = 0.0;
#pragma unroll
            for (int w = 0; w < WPB; w++) tot += sred[w];
            out[0] = (float)tot;
        }
    }
}

extern "C" void kernel_launch(void* const* d_in, const int* in_sizes, int n_in,
                              void* d_out, int out_size) {
    const float4* x = (const float4*)d_in[0];   // clust_space [B*NPER, 4], 16B rows
    // d_in[1] (batch_idx) is sorted with equal group sizes -> pure reshape, unused.
    llfill_fused_kernel<<<NBLK, THREADS>>>(x, (float*)d_out);
}